// round 1
// baseline (speedup 1.0000x reference)
#include <cuda_runtime.h>

// Problem constants
#define B_   8
#define S_   512
#define H_   1024
#define NH_  16
#define D_   64
#define M_   (B_*S_)   // 4096 rows

// Scratch (device globals: allocation-free per harness rules)
__device__ float g_q[M_*H_];
__device__ float g_k[M_*H_];
__device__ float g_v[M_*H_];
__device__ float g_attn[M_*H_];

// ---------------------------------------------------------------------------
// SGEMM: C[M,1024] = A[M,1024] @ W[1024,1024]^T + bias   (NT, both row-major)
// 128x128 block tile, BK=8, 256 threads, 8x8 micro-tile.
// ---------------------------------------------------------------------------
__device__ __forceinline__ void sgemm_body(
    const float* __restrict__ A, const float* __restrict__ W,
    const float* __restrict__ bias, float* __restrict__ C)
{
    constexpr int N = 1024, K = 1024;
    __shared__ float As[8][128];
    __shared__ float Bs[8][128];

    const int t  = threadIdx.x;
    const int m0 = blockIdx.y * 128;
    const int n0 = blockIdx.x * 128;
    const int lr  = t >> 1;          // 0..127 : tile row to load
    const int lc4 = (t & 1) * 4;     // 0 or 4 : k sub-offset (float4)
    const float* Ap = A + (size_t)(m0 + lr) * K + lc4;
    const float* Wp = W + (size_t)(n0 + lr) * K + lc4;
    const int tx = t & 15, ty = t >> 4;

    float acc[8][8];
    #pragma unroll
    for (int i = 0; i < 8; i++)
        #pragma unroll
        for (int j = 0; j < 8; j++) acc[i][j] = 0.0f;

    for (int kt = 0; kt < K; kt += 8) {
        float4 av = *(const float4*)(Ap + kt);
        float4 wv = *(const float4*)(Wp + kt);
        As[lc4+0][lr] = av.x; As[lc4+1][lr] = av.y;
        As[lc4+2][lr] = av.z; As[lc4+3][lr] = av.w;
        Bs[lc4+0][lr] = wv.x; Bs[lc4+1][lr] = wv.y;
        Bs[lc4+2][lr] = wv.z; Bs[lc4+3][lr] = wv.w;
        __syncthreads();
        #pragma unroll
        for (int k = 0; k < 8; k++) {
            float a[8], bb[8];
            *(float4*)&a[0]  = *(const float4*)&As[k][ty*4];
            *(float4*)&a[4]  = *(const float4*)&As[k][ty*4 + 64];
            *(float4*)&bb[0] = *(const float4*)&Bs[k][tx*4];
            *(float4*)&bb[4] = *(const float4*)&Bs[k][tx*4 + 64];
            #pragma unroll
            for (int i = 0; i < 8; i++)
                #pragma unroll
                for (int j = 0; j < 8; j++)
                    acc[i][j] += a[i] * bb[j];
        }
        __syncthreads();
    }

    #pragma unroll
    for (int jh = 0; jh < 2; jh++) {
        const int n = n0 + tx*4 + jh*64;
        const float4 bv = *(const float4*)(bias + n);
        #pragma unroll
        for (int ih = 0; ih < 2; ih++) {
            #pragma unroll
            for (int ii = 0; ii < 4; ii++) {
                const int m = m0 + ty*4 + ih*64 + ii;
                float4 r;
                r.x = acc[ih*4+ii][jh*4+0] + bv.x;
                r.y = acc[ih*4+ii][jh*4+1] + bv.y;
                r.z = acc[ih*4+ii][jh*4+2] + bv.z;
                r.w = acc[ih*4+ii][jh*4+3] + bv.w;
                *(float4*)(C + (size_t)m * N + n) = r;
            }
        }
    }
}

__global__ __launch_bounds__(256) void sgemm_qkv_kernel(
    const float* __restrict__ q, const float* __restrict__ k, const float* __restrict__ v,
    const float* __restrict__ Wq, const float* __restrict__ Wk, const float* __restrict__ Wv,
    const float* __restrict__ bq, const float* __restrict__ bk, const float* __restrict__ bv)
{
    const float* A; const float* W; const float* bias; float* C;
    if (blockIdx.z == 0)      { A = q; W = Wq; bias = bq; C = g_q; }
    else if (blockIdx.z == 1) { A = k; W = Wk; bias = bk; C = g_k; }
    else                      { A = v; W = Wv; bias = bv; C = g_v; }
    sgemm_body(A, W, bias, C);
}

__global__ __launch_bounds__(256) void sgemm_out_kernel(
    const float* __restrict__ Wo, const float* __restrict__ bo, float* __restrict__ out)
{
    sgemm_body(g_attn, Wo, bo, out);
}

// ---------------------------------------------------------------------------
// Attention: one block per (b, h, 32-query tile). 256 threads.
// Phase A: scores[32][512] = Q Kt / 8     (GEMM 32x512x64, smem panel)
// Phase B: masked softmax + large/sim/top transform (in place)
// Phase C: out[32][64] = A @ V            (GEMM 32x64x512)
// ---------------------------------------------------------------------------
#define SS_STRIDE 516   // 512 padded -> conflict-free row access in softmax
#define SQ_STRIDE 36    // 32 padded
#define SK_STRIDE 132   // 128 padded
#define SV_STRIDE 68    // 64 padded
#define ATTN_SMEM_FLOATS (32*SS_STRIDE + 64*SQ_STRIDE + 64*SK_STRIDE)
#define ATTN_SMEM_BYTES  (ATTN_SMEM_FLOATS * 4)

__global__ __launch_bounds__(256) void attn_kernel(
    const float* __restrict__ mask, const int* __restrict__ lena,
    const float* __restrict__ kg, const float* __restrict__ hy,
    const int* __restrict__ layerp)
{
    extern __shared__ float sm[];
    float* sS  = sm;                       // 32 x SS_STRIDE
    float* sQt = sm + 32*SS_STRIDE;        // 64 x SQ_STRIDE  (Q transposed: [d][i])
    float* sKt = sQt + 64*SQ_STRIDE;       // 64 x SK_STRIDE  (K transposed: [d][j]); reused as V

    const int t  = threadIdx.x;
    const int b  = blockIdx.z;
    const int h  = blockIdx.y;
    const int q0 = blockIdx.x * 32;

    // ---- Load Q block (32 x 64), store transposed sQt[d][i] ----
    {
        const int i  = t >> 3;           // 0..31
        const int d0 = (t & 7) * 8;      // 0..56
        const float* qp = g_q + ((size_t)(b*S_ + q0 + i)) * H_ + h*D_ + d0;
        float4 v0 = *(const float4*)qp;
        float4 v1 = *(const float4*)(qp + 4);
        sQt[(d0+0)*SQ_STRIDE+i] = v0.x; sQt[(d0+1)*SQ_STRIDE+i] = v0.y;
        sQt[(d0+2)*SQ_STRIDE+i] = v0.z; sQt[(d0+3)*SQ_STRIDE+i] = v0.w;
        sQt[(d0+4)*SQ_STRIDE+i] = v1.x; sQt[(d0+5)*SQ_STRIDE+i] = v1.y;
        sQt[(d0+6)*SQ_STRIDE+i] = v1.z; sQt[(d0+7)*SQ_STRIDE+i] = v1.w;
    }
    __syncthreads();

    // ---- Phase A: scores ----
    const int ti = t >> 5, tj = t & 31;       // 8 x 32 thread grid
    const int rm = ti * 4, cn = tj * 4;       // 4x4 micro-tile (i in 0..31, j in 0..127)

    #pragma unroll 1
    for (int p = 0; p < 4; p++) {
        // load 128 K rows (j = p*128..p*128+127), transposed into sKt[d][jj]
        {
            const int jj = t >> 1;            // 0..127
            const int d0 = (t & 1) * 32;      // 0 or 32
            const float* kp = g_k + ((size_t)(b*S_ + p*128 + jj)) * H_ + h*D_ + d0;
            #pragma unroll
            for (int u = 0; u < 8; u++) {
                float4 v = *(const float4*)(kp + u*4);
                const int d = d0 + u*4;
                sKt[(d+0)*SK_STRIDE+jj] = v.x; sKt[(d+1)*SK_STRIDE+jj] = v.y;
                sKt[(d+2)*SK_STRIDE+jj] = v.z; sKt[(d+3)*SK_STRIDE+jj] = v.w;
            }
        }
        __syncthreads();

        float acc[4][4];
        #pragma unroll
        for (int i = 0; i < 4; i++)
            #pragma unroll
            for (int j = 0; j < 4; j++) acc[i][j] = 0.0f;

        #pragma unroll
        for (int d = 0; d < 64; d++) {
            float a[4], bb[4];
            *(float4*)a  = *(const float4*)&sQt[d*SQ_STRIDE + rm];
            *(float4*)bb = *(const float4*)&sKt[d*SK_STRIDE + cn];
            #pragma unroll
            for (int i = 0; i < 4; i++)
                #pragma unroll
                for (int j = 0; j < 4; j++)
                    acc[i][j] += a[i] * bb[j];
        }
        #pragma unroll
        for (int ii = 0; ii < 4; ii++) {
            float4 r = make_float4(acc[ii][0]*0.125f, acc[ii][1]*0.125f,
                                   acc[ii][2]*0.125f, acc[ii][3]*0.125f);
            *(float4*)&sS[(rm+ii)*SS_STRIDE + p*128 + cn] = r;
        }
        __syncthreads();
    }

    // ---- Phase B: softmax + transform (8 threads per row) ----
    {
        const int r  = t >> 3;       // row 0..31
        const int u  = t & 7;        // lane within row-group (8-lane aligned in warp)
        const int qi = q0 + r;
        const int l  = lena[b];
        const int ly = layerp[0];
        const float hy0 = hy[ly*3+0], hy1 = hy[ly*3+1], cc = hy[ly*3+2];
        const float* mrow = mask + ((size_t)b*S_ + qi) * S_;
        const float* srow = kg + (((size_t)b*2 + 0) * S_ + qi) * S_;
        const float* trow = kg + (((size_t)b*2 + 1) * S_ + qi) * S_;
        float* ss = sS + r * SS_STRIDE;

        float mx = -1e30f;
        #pragma unroll
        for (int w = 0; w < 64; w++) {
            const int j = u + 8*w;
            float val = ss[j] + mrow[j];
            ss[j] = val;
            mx = fmaxf(mx, val);
        }
        mx = fmaxf(mx, __shfl_xor_sync(0xffffffffu, mx, 1));
        mx = fmaxf(mx, __shfl_xor_sync(0xffffffffu, mx, 2));
        mx = fmaxf(mx, __shfl_xor_sync(0xffffffffu, mx, 4));

        float sum = 0.0f;
        #pragma unroll
        for (int w = 0; w < 64; w++) {
            const int j = u + 8*w;
            float e = expf(ss[j] - mx);
            ss[j] = e;
            sum += e;
        }
        sum += __shfl_xor_sync(0xffffffffu, sum, 1);
        sum += __shfl_xor_sync(0xffffffffu, sum, 2);
        sum += __shfl_xor_sync(0xffffffffu, sum, 4);
        const float inv = 1.0f / sum;

        const bool rowa_i = (qi >= 1) && (qi < l - 1);
        const bool cola_i = (qi >= l) && (qi < S_ - 1);
        #pragma unroll
        for (int w = 0; w < 64; w++) {
            const int j = u + 8*w;
            const bool rowa_j = (j >= 1) && (j < l - 1);
            const bool cola_j = (j >= l) && (j < S_ - 1);
            const float lg = ((rowa_i && cola_j) || (rowa_j && cola_i)) ? cc : 1.0f;
            ss[j] = ss[j] * inv * lg + hy0 * srow[j] + hy1 * trow[j];
        }
    }
    __syncthreads();

    // ---- Phase C: out[32][64] = A[32,512] @ V[512,64] ----
    float* sV = sKt;                      // reuse, stride SV_STRIDE
    const int ti2 = t >> 4;               // 0..15 -> rows ti2*2, ti2*2+1
    const int tn  = (t & 15) * 4;         // 0..60
    float oacc[2][4] = {{0,0,0,0},{0,0,0,0}};

    #pragma unroll 1
    for (int kt = 0; kt < 8; kt++) {
        {
            const int kk  = t >> 2;       // 0..63
            const int n0l = (t & 3) * 16; // 0..48
            const float* vp = g_v + ((size_t)(b*S_ + kt*64 + kk)) * H_ + h*D_ + n0l;
            #pragma unroll
            for (int u2 = 0; u2 < 4; u2++)
                *(float4*)&sV[kk*SV_STRIDE + n0l + u2*4] = *(const float4*)(vp + u2*4);
        }
        __syncthreads();
        #pragma unroll
        for (int kk = 0; kk < 64; kk++) {
            const float a0 = sS[(ti2*2+0)*SS_STRIDE + kt*64 + kk];
            const float a1 = sS[(ti2*2+1)*SS_STRIDE + kt*64 + kk];
            const float4 bv4 = *(const float4*)&sV[kk*SV_STRIDE + tn];
            oacc[0][0] += a0 * bv4.x; oacc[0][1] += a0 * bv4.y;
            oacc[0][2] += a0 * bv4.z; oacc[0][3] += a0 * bv4.w;
            oacc[1][0] += a1 * bv4.x; oacc[1][1] += a1 * bv4.y;
            oacc[1][2] += a1 * bv4.z; oacc[1][3] += a1 * bv4.w;
        }
        __syncthreads();
    }

    #pragma unroll
    for (int ii = 0; ii < 2; ii++) {
        float4 r = make_float4(oacc[ii][0], oacc[ii][1], oacc[ii][2], oacc[ii][3]);
        *(float4*)&g_attn[((size_t)(b*S_ + q0 + ti2*2 + ii)) * H_ + h*D_ + tn] = r;
    }
}

// ---------------------------------------------------------------------------
extern "C" void kernel_launch(void* const* d_in, const int* in_sizes, int n_in,
                              void* d_out, int out_size)
{
    const float* query = (const float*)d_in[0];
    const float* key   = (const float*)d_in[1];
    const float* value = (const float*)d_in[2];
    const float* mask  = (const float*)d_in[3];
    const int*   lena  = (const int*)  d_in[4];
    const float* kg    = (const float*)d_in[5];
    const float* hy    = (const float*)d_in[6];
    const int*   layer = (const int*)  d_in[7];
    const float* Wq    = (const float*)d_in[8];
    const float* bq    = (const float*)d_in[9];
    const float* Wk    = (const float*)d_in[10];
    const float* bk    = (const float*)d_in[11];
    const float* Wv    = (const float*)d_in[12];
    const float* bv    = (const float*)d_in[13];
    const float* Wo    = (const float*)d_in[14];
    const float* bo    = (const float*)d_in[15];
    float* out = (float*)d_out;

    cudaFuncSetAttribute(attn_kernel, cudaFuncAttributeMaxDynamicSharedMemorySize,
                         ATTN_SMEM_BYTES);

    // QKV projections: grid.z selects q/k/v
    dim3 gQKV(1024/128, M_/128, 3);
    sgemm_qkv_kernel<<<gQKV, 256>>>(query, key, value, Wq, Wk, Wv, bq, bk, bv);

    // Attention
    dim3 gA(S_/32, NH_, B_);
    attn_kernel<<<gA, 256, ATTN_SMEM_BYTES>>>(mask, lena, kg, hy, layer);

    // Output projection
    dim3 gO(1024/128, M_/128, 1);
    sgemm_out_kernel<<<gO, 256>>>(Wo, bo, out);
}

// round 3
// speedup vs baseline: 1.4536x; 1.4536x over previous
#include <cuda_runtime.h>
#include <cuda_bf16.h>
#include <cstdint>

// Problem constants
#define B_   8
#define S_   512
#define H_   1024
#define NH_  16
#define D_   64
#define M_   (B_*S_)   // 4096 rows

// ---------------------------------------------------------------------------
// Scratch (device globals: allocation-free per harness rules)
// ---------------------------------------------------------------------------
__device__ float g_q[M_*H_];
__device__ float g_k[M_*H_];
__device__ float g_v[M_*H_];
__device__ float g_attn[M_*H_];

// ---------------------------------------------------------------------------
// helpers
// ---------------------------------------------------------------------------
__device__ __forceinline__ uint32_t smem_u32(const void* p) {
    uint32_t a;
    asm("{ .reg .u64 t; cvta.to.shared.u64 t, %1; cvt.u32.u64 %0, t; }"
        : "=r"(a) : "l"(p));
    return a;
}

#define LDSM_X4(r0, r1, r2, r3, addr)                                          \
    asm volatile("ldmatrix.sync.aligned.m8n8.x4.shared.b16 {%0,%1,%2,%3}, [%4];" \
                 : "=r"(r0), "=r"(r1), "=r"(r2), "=r"(r3) : "r"(addr))

#define MMA_BF16(d, a, b)                                                      \
    asm volatile("mma.sync.aligned.m16n8k16.row.col.f32.bf16.bf16.f32 "        \
                 "{%0,%1,%2,%3}, {%4,%5,%6,%7}, {%8,%9}, {%0,%1,%2,%3};"       \
                 : "+f"((d)[0]), "+f"((d)[1]), "+f"((d)[2]), "+f"((d)[3])      \
                 : "r"((a)[0]), "r"((a)[1]), "r"((a)[2]), "r"((a)[3]),         \
                   "r"((b)[0]), "r"((b)[1]))

__device__ __forceinline__ uint32_t pack_bf16(__nv_bfloat16 lo, __nv_bfloat16 hi) {
    uint16_t l = __bfloat16_as_ushort(lo);
    uint16_t h = __bfloat16_as_ushort(hi);
    return (uint32_t)l | ((uint32_t)h << 16);
}

// ---------------------------------------------------------------------------
// bf16x3 mma.sync GEMM: C[M,1024] = A[M,1024] @ W[1024,1024]^T + bias
// fp32 inputs; hi/lo bf16 split fused into the smem fill.
// CTA tile 128x128, 8 warps (warp tile 32x64), K-chunk 32, double buffer.
// smem rows padded to 40 bf16 (80B) -> conflict-free ldmatrix.
// ---------------------------------------------------------------------------
#define GSTRIDE 40                       // bf16 elems per smem row
#define PIECE_B (128*GSTRIDE*2)          // 10240 bytes per (matrix,split) piece
#define BUF_B   (4*PIECE_B)              // Ah,Al,Wh,Wl = 40960 bytes
#define GEMM_SMEM_BYTES (2*BUF_B)        // 81920

__device__ __forceinline__ void gemm_bf16x3_body(
    const float* __restrict__ A, const float* __restrict__ W,
    const float* __restrict__ bias, float* __restrict__ C)
{
    extern __shared__ __align__(16) char gsm[];
    const uint32_t ub = smem_u32(gsm);

    const int t    = threadIdx.x;
    const int lane = t & 31;
    const int w    = t >> 5;
    const int m0 = blockIdx.y * 128;
    const int n0 = blockIdx.x * 128;
    const int wm0 = (w >> 1) * 32;   // warp row offset in CTA tile
    const int wn0 = (w & 1) * 64;    // warp col offset

    // ---- global-load / smem-store geometry (fill) ----
    const int lr = t >> 1;           // 0..127 : tile row this thread fills
    const int lk = (t & 1) * 16;     // 0 or 16: k-half
    const float* Ap = A + (size_t)(m0 + lr) * 1024 + lk;
    const float* Wp = W + (size_t)(n0 + lr) * 1024 + lk;
    const uint32_t fill_off = (uint32_t)(lr * GSTRIDE + lk) * 2;  // bytes

    // ---- ldmatrix lane address bases (byte offsets within a piece) ----
    const uint32_t a_lane = (uint32_t)(((lane & 15) * GSTRIDE + ((lane >> 4) << 3)) * 2);
    const uint32_t b_lane = (uint32_t)(((((lane & 7) | ((lane >> 4) << 3))) * GSTRIDE
                                       + (((lane >> 3) & 1) << 3)) * 2);
    const uint32_t aBase0 = ub + (uint32_t)(wm0 * GSTRIDE * 2) + a_lane;
    const uint32_t bBase0 = ub + (uint32_t)(wn0 * GSTRIDE * 2) + b_lane;

    float acc[2][8][4];
    #pragma unroll
    for (int mi = 0; mi < 2; mi++)
        #pragma unroll
        for (int ni = 0; ni < 8; ni++)
            #pragma unroll
            for (int j = 0; j < 4; j++) acc[mi][ni][j] = 0.0f;

    float4 ar[4], wr[4];

    // -------- fill macros --------
    #define GLOAD(c) do {                                                      \
        const float* _a = Ap + (c) * 32;                                       \
        const float* _w = Wp + (c) * 32;                                       \
        _Pragma("unroll")                                                      \
        for (int i = 0; i < 4; i++) {                                          \
            ar[i] = *(const float4*)(_a + i * 4);                              \
            wr[i] = *(const float4*)(_w + i * 4);                              \
        }                                                                      \
    } while (0)

    #define CVTSTORE(src, dstH) do {                                           \
        uint32_t ph[8], pl[8];                                                  \
        _Pragma("unroll")                                                       \
        for (int i = 0; i < 4; i++) {                                           \
            float f0 = src[i].x, f1 = src[i].y, f2 = src[i].z, f3 = src[i].w;   \
            __nv_bfloat16 h0 = __float2bfloat16(f0);                            \
            __nv_bfloat16 h1 = __float2bfloat16(f1);                            \
            __nv_bfloat16 h2 = __float2bfloat16(f2);                            \
            __nv_bfloat16 h3 = __float2bfloat16(f3);                            \
            __nv_bfloat16 l0 = __float2bfloat16(f0 - __bfloat162float(h0));     \
            __nv_bfloat16 l1 = __float2bfloat16(f1 - __bfloat162float(h1));     \
            __nv_bfloat16 l2 = __float2bfloat16(f2 - __bfloat162float(h2));     \
            __nv_bfloat16 l3 = __float2bfloat16(f3 - __bfloat162float(h3));     \
            ph[i*2+0] = pack_bf16(h0, h1); ph[i*2+1] = pack_bf16(h2, h3);       \
            pl[i*2+0] = pack_bf16(l0, l1); pl[i*2+1] = pack_bf16(l2, l3);       \
        }                                                                       \
        char* _dh = (char*)gsm + (dstH) + fill_off;                             \
        *(uint4*)(_dh)                 = make_uint4(ph[0], ph[1], ph[2], ph[3]); \
        *(uint4*)(_dh + 16)            = make_uint4(ph[4], ph[5], ph[6], ph[7]); \
        *(uint4*)(_dh + PIECE_B)       = make_uint4(pl[0], pl[1], pl[2], pl[3]); \
        *(uint4*)(_dh + PIECE_B + 16)  = make_uint4(pl[4], pl[5], pl[6], pl[7]); \
    } while (0)

    #define SSTORE(bf) do {                                                    \
        CVTSTORE(ar, (uint32_t)((bf) * BUF_B));                                \
        CVTSTORE(wr, (uint32_t)((bf) * BUF_B + 2 * PIECE_B));                  \
    } while (0)

    // -------- prologue --------
    GLOAD(0);
    SSTORE(0);
    __syncthreads();

    #pragma unroll 1
    for (int c = 0; c < 32; c++) {
        const int bf = c & 1;
        if (c < 31) GLOAD(c + 1);

        const uint32_t bo = (uint32_t)(bf * BUF_B);
        const uint32_t aH = aBase0 + bo;
        const uint32_t aL = aH + PIECE_B;
        const uint32_t bH = bBase0 + bo + 2 * PIECE_B;
        const uint32_t bL = bH + PIECE_B;

        #pragma unroll
        for (int ks = 0; ks < 2; ks++) {
            const uint32_t ko = (uint32_t)(ks * 32);   // 16 bf16 = 32 bytes
            uint32_t fAh[2][4], fAl[2][4], fWh[8][2], fWl[8][2];
            #pragma unroll
            for (int mi = 0; mi < 2; mi++) {
                const uint32_t mo = (uint32_t)(mi * 16 * GSTRIDE * 2);
                LDSM_X4(fAh[mi][0], fAh[mi][1], fAh[mi][2], fAh[mi][3], aH + mo + ko);
                LDSM_X4(fAl[mi][0], fAl[mi][1], fAl[mi][2], fAl[mi][3], aL + mo + ko);
            }
            #pragma unroll
            for (int p = 0; p < 4; p++) {
                const uint32_t po = (uint32_t)(p * 16 * GSTRIDE * 2);
                LDSM_X4(fWh[2*p][0], fWh[2*p][1], fWh[2*p+1][0], fWh[2*p+1][1], bH + po + ko);
                LDSM_X4(fWl[2*p][0], fWl[2*p][1], fWl[2*p+1][0], fWl[2*p+1][1], bL + po + ko);
            }
            #pragma unroll
            for (int mi = 0; mi < 2; mi++)
                #pragma unroll
                for (int ni = 0; ni < 8; ni++) {
                    MMA_BF16(acc[mi][ni], fAh[mi], fWh[ni]);
                    MMA_BF16(acc[mi][ni], fAh[mi], fWl[ni]);
                    MMA_BF16(acc[mi][ni], fAl[mi], fWh[ni]);
                }
        }

        if (c < 31) SSTORE((c + 1) & 1);
        __syncthreads();
    }

    // -------- epilogue --------
    const int cr = lane >> 2;           // 0..7
    const int cc = (lane & 3) * 2;
    #pragma unroll
    for (int mi = 0; mi < 2; mi++) {
        const int r0 = m0 + wm0 + mi * 16 + cr;
        #pragma unroll
        for (int ni = 0; ni < 8; ni++) {
            const int nc = n0 + wn0 + ni * 8 + cc;
            const float b0 = bias[nc], b1 = bias[nc + 1];
            float2 v0 = make_float2(acc[mi][ni][0] + b0, acc[mi][ni][1] + b1);
            float2 v1 = make_float2(acc[mi][ni][2] + b0, acc[mi][ni][3] + b1);
            *(float2*)(C + (size_t)r0 * 1024 + nc)       = v0;
            *(float2*)(C + (size_t)(r0 + 8) * 1024 + nc) = v1;
        }
    }
    #undef GLOAD
    #undef CVTSTORE
    #undef SSTORE
}

__global__ __launch_bounds__(256) void gemm_qkv_kernel(
    const float* __restrict__ q, const float* __restrict__ k, const float* __restrict__ v,
    const float* __restrict__ Wq, const float* __restrict__ Wk, const float* __restrict__ Wv,
    const float* __restrict__ bq, const float* __restrict__ bk, const float* __restrict__ bv)
{
    if (blockIdx.z == 0)      gemm_bf16x3_body(q, Wq, bq, g_q);
    else if (blockIdx.z == 1) gemm_bf16x3_body(k, Wk, bk, g_k);
    else                      gemm_bf16x3_body(v, Wv, bv, g_v);
}

__global__ __launch_bounds__(256) void gemm_out_kernel(
    const float* __restrict__ Wo, const float* __restrict__ bo, float* __restrict__ out)
{
    gemm_bf16x3_body(g_attn, Wo, bo, out);
}

// ---------------------------------------------------------------------------
// Attention: one block per (b, h, 32-query tile). 256 threads. (unchanged)
// ---------------------------------------------------------------------------
#define SS_STRIDE 516
#define SQ_STRIDE 36
#define SK_STRIDE 132
#define SV_STRIDE 68
#define ATTN_SMEM_FLOATS (32*SS_STRIDE + 64*SQ_STRIDE + 64*SK_STRIDE)
#define ATTN_SMEM_BYTES  (ATTN_SMEM_FLOATS * 4)

__global__ __launch_bounds__(256) void attn_kernel(
    const float* __restrict__ mask, const int* __restrict__ lena,
    const float* __restrict__ kg, const float* __restrict__ hy,
    const int* __restrict__ layerp)
{
    extern __shared__ float sm[];
    float* sS  = sm;
    float* sQt = sm + 32*SS_STRIDE;
    float* sKt = sQt + 64*SQ_STRIDE;

    const int t  = threadIdx.x;
    const int b  = blockIdx.z;
    const int h  = blockIdx.y;
    const int q0 = blockIdx.x * 32;

    {
        const int i  = t >> 3;
        const int d0 = (t & 7) * 8;
        const float* qp = g_q + ((size_t)(b*S_ + q0 + i)) * H_ + h*D_ + d0;
        float4 v0 = *(const float4*)qp;
        float4 v1 = *(const float4*)(qp + 4);
        sQt[(d0+0)*SQ_STRIDE+i] = v0.x; sQt[(d0+1)*SQ_STRIDE+i] = v0.y;
        sQt[(d0+2)*SQ_STRIDE+i] = v0.z; sQt[(d0+3)*SQ_STRIDE+i] = v0.w;
        sQt[(d0+4)*SQ_STRIDE+i] = v1.x; sQt[(d0+5)*SQ_STRIDE+i] = v1.y;
        sQt[(d0+6)*SQ_STRIDE+i] = v1.z; sQt[(d0+7)*SQ_STRIDE+i] = v1.w;
    }
    __syncthreads();

    const int ti = t >> 5, tj = t & 31;
    const int rm = ti * 4, cn = tj * 4;

    #pragma unroll 1
    for (int p = 0; p < 4; p++) {
        {
            const int jj = t >> 1;
            const int d0 = (t & 1) * 32;
            const float* kp = g_k + ((size_t)(b*S_ + p*128 + jj)) * H_ + h*D_ + d0;
            #pragma unroll
            for (int u = 0; u < 8; u++) {
                float4 v = *(const float4*)(kp + u*4);
                const int d = d0 + u*4;
                sKt[(d+0)*SK_STRIDE+jj] = v.x; sKt[(d+1)*SK_STRIDE+jj] = v.y;
                sKt[(d+2)*SK_STRIDE+jj] = v.z; sKt[(d+3)*SK_STRIDE+jj] = v.w;
            }
        }
        __syncthreads();

        float acc[4][4];
        #pragma unroll
        for (int i = 0; i < 4; i++)
            #pragma unroll
            for (int j = 0; j < 4; j++) acc[i][j] = 0.0f;

        #pragma unroll
        for (int d = 0; d < 64; d++) {
            float a[4], bb[4];
            *(float4*)a  = *(const float4*)&sQt[d*SQ_STRIDE + rm];
            *(float4*)bb = *(const float4*)&sKt[d*SK_STRIDE + cn];
            #pragma unroll
            for (int i = 0; i < 4; i++)
                #pragma unroll
                for (int j = 0; j < 4; j++)
                    acc[i][j] += a[i] * bb[j];
        }
        #pragma unroll
        for (int ii = 0; ii < 4; ii++) {
            float4 r = make_float4(acc[ii][0]*0.125f, acc[ii][1]*0.125f,
                                   acc[ii][2]*0.125f, acc[ii][3]*0.125f);
            *(float4*)&sS[(rm+ii)*SS_STRIDE + p*128 + cn] = r;
        }
        __syncthreads();
    }

    {
        const int r  = t >> 3;
        const int u  = t & 7;
        const int qi = q0 + r;
        const int l  = lena[b];
        const int ly = layerp[0];
        const float hy0 = hy[ly*3+0], hy1 = hy[ly*3+1], cc = hy[ly*3+2];
        const float* mrow = mask + ((size_t)b*S_ + qi) * S_;
        const float* srow = kg + (((size_t)b*2 + 0) * S_ + qi) * S_;
        const float* trow = kg + (((size_t)b*2 + 1) * S_ + qi) * S_;
        float* ss = sS + r * SS_STRIDE;

        float mx = -1e30f;
        #pragma unroll
        for (int w2 = 0; w2 < 64; w2++) {
            const int j = u + 8*w2;
            float val = ss[j] + mrow[j];
            ss[j] = val;
            mx = fmaxf(mx, val);
        }
        mx = fmaxf(mx, __shfl_xor_sync(0xffffffffu, mx, 1));
        mx = fmaxf(mx, __shfl_xor_sync(0xffffffffu, mx, 2));
        mx = fmaxf(mx, __shfl_xor_sync(0xffffffffu, mx, 4));

        float sum = 0.0f;
        #pragma unroll
        for (int w2 = 0; w2 < 64; w2++) {
            const int j = u + 8*w2;
            float e = expf(ss[j] - mx);
            ss[j] = e;
            sum += e;
        }
        sum += __shfl_xor_sync(0xffffffffu, sum, 1);
        sum += __shfl_xor_sync(0xffffffffu, sum, 2);
        sum += __shfl_xor_sync(0xffffffffu, sum, 4);
        const float inv = 1.0f / sum;

        const bool rowa_i = (qi >= 1) && (qi < l - 1);
        const bool cola_i = (qi >= l) && (qi < S_ - 1);
        #pragma unroll
        for (int w2 = 0; w2 < 64; w2++) {
            const int j = u + 8*w2;
            const bool rowa_j = (j >= 1) && (j < l - 1);
            const bool cola_j = (j >= l) && (j < S_ - 1);
            const float lg = ((rowa_i && cola_j) || (rowa_j && cola_i)) ? cc : 1.0f;
            ss[j] = ss[j] * inv * lg + hy0 * srow[j] + hy1 * trow[j];
        }
    }
    __syncthreads();

    float* sV = sKt;
    const int ti2 = t >> 4;
    const int tn  = (t & 15) * 4;
    float oacc[2][4] = {{0,0,0,0},{0,0,0,0}};

    #pragma unroll 1
    for (int kt = 0; kt < 8; kt++) {
        {
            const int kk  = t >> 2;
            const int n0l = (t & 3) * 16;
            const float* vp = g_v + ((size_t)(b*S_ + kt*64 + kk)) * H_ + h*D_ + n0l;
            #pragma unroll
            for (int u2 = 0; u2 < 4; u2++)
                *(float4*)&sV[kk*SV_STRIDE + n0l + u2*4] = *(const float4*)(vp + u2*4);
        }
        __syncthreads();
        #pragma unroll
        for (int kk = 0; kk < 64; kk++) {
            const float a0 = sS[(ti2*2+0)*SS_STRIDE + kt*64 + kk];
            const float a1 = sS[(ti2*2+1)*SS_STRIDE + kt*64 + kk];
            const float4 bv4 = *(const float4*)&sV[kk*SV_STRIDE + tn];
            oacc[0][0] += a0 * bv4.x; oacc[0][1] += a0 * bv4.y;
            oacc[0][2] += a0 * bv4.z; oacc[0][3] += a0 * bv4.w;
            oacc[1][0] += a1 * bv4.x; oacc[1][1] += a1 * bv4.y;
            oacc[1][2] += a1 * bv4.z; oacc[1][3] += a1 * bv4.w;
        }
        __syncthreads();
    }

    #pragma unroll
    for (int ii = 0; ii < 2; ii++) {
        float4 r = make_float4(oacc[ii][0], oacc[ii][1], oacc[ii][2], oacc[ii][3]);
        *(float4*)&g_attn[((size_t)(b*S_ + q0 + ti2*2 + ii)) * H_ + h*D_ + tn] = r;
    }
}

// ---------------------------------------------------------------------------
extern "C" void kernel_launch(void* const* d_in, const int* in_sizes, int n_in,
                              void* d_out, int out_size)
{
    const float* query = (const float*)d_in[0];
    const float* key   = (const float*)d_in[1];
    const float* value = (const float*)d_in[2];
    const float* mask  = (const float*)d_in[3];
    const int*   lena  = (const int*)  d_in[4];
    const float* kg    = (const float*)d_in[5];
    const float* hy    = (const float*)d_in[6];
    const int*   layer = (const int*)  d_in[7];
    const float* Wq    = (const float*)d_in[8];
    const float* bq    = (const float*)d_in[9];
    const float* Wk    = (const float*)d_in[10];
    const float* bk    = (const float*)d_in[11];
    const float* Wv    = (const float*)d_in[12];
    const float* bv    = (const float*)d_in[13];
    const float* Wo    = (const float*)d_in[14];
    const float* bo    = (const float*)d_in[15];
    float* out = (float*)d_out;

    cudaFuncSetAttribute(attn_kernel, cudaFuncAttributeMaxDynamicSharedMemorySize,
                         ATTN_SMEM_BYTES);
    cudaFuncSetAttribute(gemm_qkv_kernel, cudaFuncAttributeMaxDynamicSharedMemorySize,
                         GEMM_SMEM_BYTES);
    cudaFuncSetAttribute(gemm_out_kernel, cudaFuncAttributeMaxDynamicSharedMemorySize,
                         GEMM_SMEM_BYTES);

    // QKV projections on tensor cores (bf16x3 via mma.sync)
    dim3 gQKV(1024/128, M_/128, 3);
    gemm_qkv_kernel<<<gQKV, 256, GEMM_SMEM_BYTES>>>(query, key, value,
                                                    Wq, Wk, Wv, bq, bk, bv);

    // Attention
    dim3 gA(S_/32, NH_, B_);
    attn_kernel<<<gA, 256, ATTN_SMEM_BYTES>>>(mask, lena, kg, hy, layer);

    // Output projection
    dim3 gO(1024/128, M_/128, 1);
    gemm_out_kernel<<<gO, 256, GEMM_SMEM_BYTES>>>(Wo, bo, out);
}